// round 11
// baseline (speedup 1.0000x reference)
#include <cuda_runtime.h>
#include <math.h>

#define NRAYS   10000
#define NSTEPS  768
#define Zn      32
#define Yn      512
#define Xn      512
#define RPB     4                         // rays per block (4 warps per ray)
#define TPB     (RPB * 128)               // 512 threads
#define NBLK    (NRAYS / RPB)             // 2500

// Per-block partial sums [l1, l2, absrel]. Every block writes its slot each
// launch before any reader -> no init needed.
__device__ float    g_partials[NBLK * 3];
__device__ unsigned g_count = 0;          // reset by the last block each launch

__global__ void __launch_bounds__(TPB)
ray_march_kernel(const float* __restrict__ grid,     // [5,32,512,512] (T,Z,Y,X)
                 const float* __restrict__ origin,   // [5,3]
                 const float* __restrict__ pts,      // [NRAYS,3]
                 const int*   __restrict__ tindex,   // [NRAYS]
                 float*       __restrict__ out)      // [3]
{
    const int tid  = threadIdx.x;
    const int warp = tid >> 5;
    const int lane = tid & 31;
    const int r    = warp >> 2;           // ray slot within block (0..3)
    const int wg   = warp & 3;            // warp within ray (0..3)
    const int ray  = blockIdx.x * RPB + r;   // 2500*4 = 10000 exactly

    // --- per-ray setup (all 128 threads of the ray redundantly) ---
    const int ti = tindex[ray];
    const float ox = (origin[ti * 3 + 0] + 51.2f) * 5.0f;
    const float oy = (origin[ti * 3 + 1] + 51.2f) * 5.0f;
    const float oz = (origin[ti * 3 + 2] + 3.2f)  * 5.0f;
    const float px = (pts[ray * 3 + 0] + 51.2f) * 5.0f;
    const float py = (pts[ray * 3 + 1] + 51.2f) * 5.0f;
    const float pz = (pts[ray * 3 + 2] + 3.2f)  * 5.0f;

    const float dx = px - ox, dy = py - oy, dz = pz - oz;
    const float gt = sqrtf(dx * dx + dy * dy + dz * dz);
    const float inv = 1.0f / fmaxf(gt, 1e-6f);
    const float ux = dx * inv, uy = dy * inv, uz = dz * inv;

    const float* __restrict__ slice = grid + (size_t)ti * (Zn * Yn * Xn);

    __shared__ float sS[16], sP[16];      // per-warp chunk tau-sum / weighted sum
    __shared__ int   sInb[RPB];           // last-step in-bounds flag per ray
    __shared__ int   sDone[RPB];
    __shared__ float sL[RPB][3];

    const bool combiner = (wg == 0) && (lane == 0);   // threads 0,128,256,384
    float T = 1.0f, pred = 0.0f;          // live only in combiner thread
    if (combiner) sDone[r] = 0;
    __syncthreads();

    // 128 steps per chunk; thread handles step base + wg*32 + lane.
    // ~all rays finish in one chunk (box exit exact, or cum-tau ~51 >> 28).
    for (int base = 0; base < NSTEPS; base += 128) {
        const bool done = (sDone[r] != 0);
        const float t = (float)(base + wg * 32 + lane) + 0.5f;

        bool inb = false;
        float tau = 0.0f;
        if (!done) {
            const int ix = __float2int_rd(ox + ux * t);
            const int iy = __float2int_rd(oy + uy * t);
            const int iz = __float2int_rd(oz + uz * t);
            inb = ((unsigned)ix < (unsigned)Xn) &
                  ((unsigned)iy < (unsigned)Yn) &
                  ((unsigned)iz < (unsigned)Zn);
            if (inb)
                tau = fmaxf(__ldg(&slice[((iz * Yn) + iy) * Xn + ix]), 0.0f);
        }

        // inclusive warp scan over this warp's 32 consecutive steps
        float cs = tau;
        #pragma unroll
        for (int off = 1; off < 32; off <<= 1) {
            float v = __shfl_up_sync(0xffffffffu, cs, off);
            if (lane >= off) cs += v;
        }
        const float excl = cs - tau;
        const float E0 = __expf(-excl);
        const float E1 = __expf(-cs);
        float c = (E0 - E1) * t;          // OOB: tau=0 -> E0==E1 -> 0 (exact)

        // butterfly: P = sum over warp of per-step w*t (local transmittance)
        #pragma unroll
        for (int off = 16; off; off >>= 1)
            c += __shfl_xor_sync(0xffffffffu, c, off);
        const float S = __shfl_sync(0xffffffffu, cs, 31);   // warp tau total

        if (lane == 0) { sS[warp] = S; sP[warp] = c; }
        if (wg == 3 && lane == 31) sInb[r] = inb ? 1 : 0;
        __syncthreads();

        if (combiner && !done) {
            // stitch 4 sub-segments: pred += T * sum_w exp(-prefix_w) * P_w
            float f = 1.0f, ch = 0.0f;
            #pragma unroll
            for (int w = 0; w < 4; w++) {
                ch += f * sP[r * 4 + w];
                f  *= __expf(-sS[r * 4 + w]);
            }
            pred += T * ch;
            T *= f;
            // Exit: last step OOB (convex box => all later OOB, exact) or
            // T < 1e-12 (dropped contribution << 1e-3 budget).
            if (!sInb[r] || T < 1e-12f) sDone[r] = 1;
        }
        __syncthreads();
        if (sDone[0] && sDone[1] && sDone[2] && sDone[3]) break;
    }

    // --- per-ray loss terms (combiner thread holds pred) ---
    if (combiner) {
        const float predm = pred * 0.2f;
        const float gtm   = gt * 0.2f;     // >= 0 always -> valid, count=NRAYS
        const float diff  = gtm - predm;
        sL[r][0] = fabsf(diff);
        sL[r][1] = diff * diff * 0.5f;
        sL[r][2] = fabsf(diff) / fmaxf(gtm, 1e-6f);
    }
    __syncthreads();
    if (tid == 0) {
        float a = 0.f, b = 0.f, d = 0.f;
        #pragma unroll
        for (int i = 0; i < RPB; i++) { a += sL[i][0]; b += sL[i][1]; d += sL[i][2]; }
        g_partials[blockIdx.x * 3 + 0] = a;
        g_partials[blockIdx.x * 3 + 1] = b;
        g_partials[blockIdx.x * 3 + 2] = d;
    }

    // --- last-block final reduction (release atomic, no CCTL.IVALL) ---
    __shared__ unsigned s_isLast;
    __syncthreads();                      // partial store (thread 0) done
    if (tid == 0) {
        unsigned old;
        asm volatile("atom.release.gpu.global.add.u32 %0, [%1], %2;"
                     : "=r"(old) : "l"(&g_count), "r"(1u) : "memory");
        s_isLast = (old == (unsigned)(NBLK - 1));
    }
    __syncthreads();

    if (s_isLast) {
        // Fixed-order strided sums: deterministic regardless of which block
        // executes this. __ldcg reads at L2 (the coherence point).
        float a = 0.f, b = 0.f, d = 0.f;
        for (int i = tid; i < NBLK; i += TPB) {
            a += __ldcg(&g_partials[i * 3 + 0]);
            b += __ldcg(&g_partials[i * 3 + 1]);
            d += __ldcg(&g_partials[i * 3 + 2]);
        }
        #pragma unroll
        for (int off = 16; off; off >>= 1) {
            a += __shfl_xor_sync(0xffffffffu, a, off);
            b += __shfl_xor_sync(0xffffffffu, b, off);
            d += __shfl_xor_sync(0xffffffffu, d, off);
        }
        __shared__ float r1[16], r2[16], r3[16];
        if (lane == 0) { r1[warp] = a; r2[warp] = b; r3[warp] = d; }
        __syncthreads();
        if (tid == 0) {
            float ta = 0.f, tb = 0.f, td = 0.f;
            #pragma unroll
            for (int i = 0; i < 16; i++) { ta += r1[i]; tb += r2[i]; td += r3[i]; }
            const float cnt = (float)NRAYS;
            out[0] = ta / cnt;
            out[1] = tb / cnt;
            out[2] = td / cnt;
            g_count = 0;                  // reset for next graph replay
        }
    }
}

extern "C" void kernel_launch(void* const* d_in, const int* in_sizes, int n_in,
                              void* d_out, int out_size)
{
    const float* grid   = (const float*)d_in[0];   // (1,5,32,512,512) f32
    const float* origin = (const float*)d_in[1];   // (1,5,3) f32
    const float* pts    = (const float*)d_in[2];   // (1,10000,3) f32
    const int*   tidx   = (const int*)d_in[3];     // (1,10000) i32
    float* out = (float*)d_out;                    // 3 floats

    ray_march_kernel<<<NBLK, TPB>>>(grid, origin, pts, tidx, out);
}

// round 12
// speedup vs baseline: 2.1375x; 2.1375x over previous
#include <cuda_runtime.h>
#include <math.h>

#define NRAYS   10000
#define NSTEPS  768
#define Zn      32
#define Yn      512
#define Xn      512
#define WPB     8                        // warps (rays) per block
#define NBLK    ((NRAYS + WPB - 1) / WPB)    // 1250

// Per-block partial sums [l1, l2, absrel]. Every block writes its slot each
// launch before any reader -> no init needed.
__device__ float    g_partials[NBLK * 3];
__device__ unsigned g_count = 0;         // reset by the last block each launch

__global__ void __launch_bounds__(WPB * 32)
ray_march_kernel(const float* __restrict__ grid,     // [5,32,512,512] (T,Z,Y,X)
                 const float* __restrict__ origin,   // [5,3]
                 const float* __restrict__ pts,      // [NRAYS,3]
                 const int*   __restrict__ tindex,   // [NRAYS]
                 float*       __restrict__ out)      // [3]
{
    const int warp = threadIdx.x >> 5;
    const int lane = threadIdx.x & 31;
    const int ray  = blockIdx.x * WPB + warp;   // grid sized exactly: always < NRAYS

    // --- per-ray setup (all lanes redundantly) ---
    const int ti = tindex[ray];
    const float ox = (origin[ti * 3 + 0] + 51.2f) * 5.0f;
    const float oy = (origin[ti * 3 + 1] + 51.2f) * 5.0f;
    const float oz = (origin[ti * 3 + 2] + 3.2f)  * 5.0f;
    const float px = (pts[ray * 3 + 0] + 51.2f) * 5.0f;
    const float py = (pts[ray * 3 + 1] + 51.2f) * 5.0f;
    const float pz = (pts[ray * 3 + 2] + 3.2f)  * 5.0f;

    const float dx = px - ox, dy = py - oy, dz = pz - oz;
    const float gt = sqrtf(dx * dx + dy * dy + dz * dz);
    const float inv = 1.0f / fmaxf(gt, 1e-6f);
    const float ux = dx * inv, uy = dy * inv, uz = dz * inv;

    const float* __restrict__ slice = grid + (size_t)ti * (Zn * Yn * Xn);

    // tau for step at param t (relu'd, 0 if OOB); inb out-param.
    auto sample = [&](float t, bool& inb) -> float {
        const int ix = __float2int_rd(ox + ux * t);
        const int iy = __float2int_rd(oy + uy * t);
        const int iz = __float2int_rd(oz + uz * t);
        inb = ((unsigned)ix < (unsigned)Xn) &
              ((unsigned)iy < (unsigned)Yn) &
              ((unsigned)iz < (unsigned)Zn);
        float v = 0.0f;
        if (inb)
            v = fmaxf(__ldg(&slice[((iz * Yn) + iy) * Xn + ix]), 0.0f);
        return v;
    };

    float T     = 1.0f;   // transmittance entering current chunk = exp(-cum)
    float predL = 0.0f;   // per-lane partial of sum(w * t)

    // 64 steps per iteration: lane l owns steps base+2l (a) and base+2l+1 (b).
    // With T_min = 3e-7 (tau_stop ~ 15), cum-tau after 64 in-bounds steps
    // ~ N(25.6, 4.3) => ~99% of rays terminate in ONE iteration.
    for (int base = 0; base < NSTEPS; base += 64) {
        const float ta = (float)(base + 2 * lane) + 0.5f;
        const float tb = ta + 1.0f;
        bool inb_a, inb_b;
        const float a = sample(ta, inb_a);   // two independent LDGs in flight
        const float b = sample(tb, inb_b);

        // inclusive warp scan of pair sums (ascending-step order)
        const float p = a + b;
        float cs = p;
        #pragma unroll
        for (int off = 1; off < 32; off <<= 1) {
            float v = __shfl_up_sync(0xffffffffu, cs, off);
            if (lane >= off) cs += v;
        }
        const float excl = cs - p;           // chunk tau before step a

        const float E0 = __expf(-excl);          // trans entering a (per-chunk)
        const float E1 = __expf(-(excl + a));    // trans entering b
        const float E2 = __expf(-cs);            // trans leaving b
        // OOB lanes: tau=0 -> adjacent E's equal -> zero contribution (exact)
        predL += T * ((E0 - E1) * ta + (E1 - E2) * tb);

        T *= __shfl_sync(0xffffffffu, E2, 31);   // fold chunk's total tau

        const unsigned bal = __ballot_sync(0xffffffffu, inb_b);
        // Exit when: last step left the box (convex => no re-entry, all later
        // tau == 0, exact) OR T < 3e-7: dropped contribution per ray
        // <= T * t_max = 3e-7 * 768 voxels ~ 5e-5 m, 4 orders under the
        // 1e-3 rel-err budget (R9 measured 1.8e-8 with the looser bound).
        if (!((bal >> 31) & 1u) || T < 3e-7f) break;
    }

    // single butterfly reduction of per-lane pred partials
    #pragma unroll
    for (int off = 16; off; off >>= 1)
        predL += __shfl_xor_sync(0xffffffffu, predL, off);

    // --- per-ray loss terms ---
    const float predm = predL * 0.2f;
    const float gtm   = gt * 0.2f;          // always >= 0 -> valid, count = NRAYS
    const float diff  = gtm - predm;
    const float l1 = fabsf(diff);
    const float l2 = diff * diff * 0.5f;
    const float ar = fabsf(diff) / fmaxf(gtm, 1e-6f);

    // Per-block reduction across WPB warps.
    __shared__ float s1[WPB], s2[WPB], s3[WPB];
    if (lane == 0) { s1[warp] = l1; s2[warp] = l2; s3[warp] = ar; }
    __syncthreads();
    if (threadIdx.x < 32) {
        float a = (lane < WPB) ? s1[lane] : 0.f;
        float b = (lane < WPB) ? s2[lane] : 0.f;
        float d = (lane < WPB) ? s3[lane] : 0.f;
        #pragma unroll
        for (int off = WPB >> 1; off; off >>= 1) {
            a += __shfl_xor_sync(0xffffffffu, a, off);
            b += __shfl_xor_sync(0xffffffffu, b, off);
            d += __shfl_xor_sync(0xffffffffu, d, off);
        }
        if (lane == 0) {
            g_partials[blockIdx.x * 3 + 0] = a;
            g_partials[blockIdx.x * 3 + 1] = b;
            g_partials[blockIdx.x * 3 + 2] = d;
        }
    }

    // --- last-block final reduction ---
    // Release atomic orders the partial stores without a gpu-scope fence
    // (avoids CCTL.IVALL chip-wide L1D flush from __threadfence).
    __shared__ unsigned s_isLast;
    __syncthreads();                     // all lane-0 stores of this block done
    if (threadIdx.x == 0) {
        unsigned old;
        asm volatile("atom.release.gpu.global.add.u32 %0, [%1], %2;"
                     : "=r"(old) : "l"(&g_count), "r"(1u) : "memory");
        s_isLast = (old == (unsigned)(NBLK - 1));
    }
    __syncthreads();

    if (s_isLast) {
        // Fixed-order strided sums: deterministic regardless of which block
        // executes this. __ldcg reads at L2 (the coherence point).
        float a = 0.f, b = 0.f, d = 0.f;
        for (int i = threadIdx.x; i < NBLK; i += WPB * 32) {
            a += __ldcg(&g_partials[i * 3 + 0]);
            b += __ldcg(&g_partials[i * 3 + 1]);
            d += __ldcg(&g_partials[i * 3 + 2]);
        }
        #pragma unroll
        for (int off = 16; off; off >>= 1) {
            a += __shfl_xor_sync(0xffffffffu, a, off);
            b += __shfl_xor_sync(0xffffffffu, b, off);
            d += __shfl_xor_sync(0xffffffffu, d, off);
        }
        if (lane == 0) { s1[warp] = a; s2[warp] = b; s3[warp] = d; }
        __syncthreads();
        if (threadIdx.x == 0) {
            float ta = 0.f, tb = 0.f, td = 0.f;
            #pragma unroll
            for (int i = 0; i < WPB; i++) { ta += s1[i]; tb += s2[i]; td += s3[i]; }
            const float cnt = (float)NRAYS;
            out[0] = ta / cnt;
            out[1] = tb / cnt;
            out[2] = td / cnt;
            g_count = 0;                 // reset for next graph replay
        }
    }
}

extern "C" void kernel_launch(void* const* d_in, const int* in_sizes, int n_in,
                              void* d_out, int out_size)
{
    const float* grid   = (const float*)d_in[0];   // (1,5,32,512,512) f32
    const float* origin = (const float*)d_in[1];   // (1,5,3) f32
    const float* pts    = (const float*)d_in[2];   // (1,10000,3) f32
    const int*   tidx   = (const int*)d_in[3];     // (1,10000) i32
    float* out = (float*)d_out;                    // 3 floats

    ray_march_kernel<<<NBLK, WPB * 32>>>(grid, origin, pts, tidx, out);
}